// round 1
// baseline (speedup 1.0000x reference)
#include <cuda_runtime.h>
#include <math.h>

#define N_NODES_C  20000
#define N_EDGES_C  320000
#define NODE_DIM_C 512
#define HIDDEN_C   512
#define N_GRAPHS_C 64
#define VEC4       (HIDDEN_C / 4)   // 128 float4 per row

// ---------------- device scratch (static, no allocations) ----------------
__device__ float g_A[N_NODES_C * HIDDEN_C];          // A = x + S x   (40 MB)
__device__ int   g_deg[N_NODES_C];
__device__ int   g_cursor[N_NODES_C];
__device__ int   g_off[N_NODES_C + 1];
__device__ int   g_srcsort[N_EDGES_C];               // src ids sorted by dst
__device__ int   g_n[N_GRAPHS_C];                    // nodes per graph
__device__ int   g_m[N_GRAPHS_C];                    // edges with dst in graph
__device__ int   g_nodeoff[N_GRAPHS_C + 1];
__device__ float g_U[N_GRAPHS_C * HIDDEN_C];
__device__ float g_P[N_GRAPHS_C * HIDDEN_C];
__device__ float g_pooled[N_GRAPHS_C * HIDDEN_C];

__device__ __forceinline__ float4 f4add(float4 a, float4 b) {
    a.x += b.x; a.y += b.y; a.z += b.z; a.w += b.w; return a;
}

// ---------------- 1. init counters ----------------
__global__ void k_init() {
    int i = blockIdx.x * blockDim.x + threadIdx.x;
    int stride = gridDim.x * blockDim.x;
    for (int j = i; j < N_NODES_C; j += stride) { g_deg[j] = 0; g_cursor[j] = 0; }
    for (int j = i; j < N_GRAPHS_C; j += stride) { g_n[j] = 0; g_m[j] = 0; }
    for (int j = i; j < N_GRAPHS_C * HIDDEN_C; j += stride) g_U[j] = 0.0f;
}

// ---------------- 2. histograms: in-degree, n_g, m_g ----------------
__global__ void k_hist(const int* __restrict__ src, const int* __restrict__ dst,
                       const int* __restrict__ batch) {
    int e = blockIdx.x * blockDim.x + threadIdx.x;
    if (e < N_EDGES_C) {
        int d = dst[e];
        atomicAdd(&g_deg[d], 1);
        atomicAdd(&g_m[batch[d]], 1);
    }
    if (e < N_NODES_C) {
        atomicAdd(&g_n[batch[e]], 1);
    }
}

// ---------------- 3. exclusive scan (single block) ----------------
__global__ void k_scan() {
    const int T = 1024;
    const int CH = (N_NODES_C + T - 1) / T;  // 20
    __shared__ int sh[T];
    int t = threadIdx.x;
    int base = t * CH;
    int sum = 0;
    for (int j = 0; j < CH; j++) {
        int idx = base + j;
        if (idx < N_NODES_C) sum += g_deg[idx];
    }
    sh[t] = sum;
    __syncthreads();
    // inclusive scan over 1024 partials
    for (int ofs = 1; ofs < T; ofs <<= 1) {
        int v = (t >= ofs) ? sh[t - ofs] : 0;
        __syncthreads();
        sh[t] += v;
        __syncthreads();
    }
    int run = (t == 0) ? 0 : sh[t - 1];
    for (int j = 0; j < CH; j++) {
        int idx = base + j;
        if (idx < N_NODES_C) { g_off[idx] = run; run += g_deg[idx]; }
    }
    if (t == T - 1) g_off[N_NODES_C] = run;
    // node offsets per graph (batch is sorted)
    if (t == 0) {
        int r = 0;
        for (int g = 0; g < N_GRAPHS_C; g++) { g_nodeoff[g] = r; r += g_n[g]; }
        g_nodeoff[N_GRAPHS_C] = r;
    }
}

// ---------------- 4. CSR fill: srcs grouped by dst ----------------
__global__ void k_fill(const int* __restrict__ src, const int* __restrict__ dst) {
    int e = blockIdx.x * blockDim.x + threadIdx.x;
    if (e < N_EDGES_C) {
        int d = dst[e];
        int p = g_off[d] + atomicAdd(&g_cursor[d], 1);
        g_srcsort[p] = src[e];
    }
}

// ---------------- 5. A = x + scatter(x)  (atomic-free gather) ----------------
// one block (128 thr) per node; thread t owns float4 column chunk t
__global__ void __launch_bounds__(VEC4) k_gatherA(const float* __restrict__ x) {
    int i = blockIdx.x;
    int t = threadIdx.x;
    const float4* x4 = (const float4*)x;
    float4 acc = x4[(long)i * VEC4 + t];
    int e0 = g_off[i], e1 = g_off[i + 1];
    for (int e = e0; e < e1; e++) {
        int s = g_srcsort[e];
        acc = f4add(acc, x4[(long)s * VEC4 + t]);
    }
    ((float4*)g_A)[(long)i * VEC4 + t] = acc;
}

// ---------------- 6. U_g = sum over graph of (A + gather(A)) ----------------
#define PARTS 16
__global__ void __launch_bounds__(VEC4) k_upool() {
    int g = blockIdx.x;
    int part = blockIdx.y;
    int t = threadIdx.x;
    int n0 = g_nodeoff[g], n1 = g_nodeoff[g + 1];
    int len = n1 - n0;
    int per = (len + PARTS - 1) / PARTS;
    int a = n0 + part * per;
    int b = a + per; if (b > n1) b = n1;
    if (a >= b) return;
    const float4* A4 = (const float4*)g_A;
    float4 acc = make_float4(0.f, 0.f, 0.f, 0.f);
    for (int i = a; i < b; i++) {
        acc = f4add(acc, A4[(long)i * VEC4 + t]);
        int e0 = g_off[i], e1 = g_off[i + 1];
        for (int e = e0; e < e1; e++) {
            int s = g_srcsort[e];
            acc = f4add(acc, A4[(long)s * VEC4 + t]);
        }
    }
    float* Urow = &g_U[g * HIDDEN_C + t * 4];
    atomicAdd(&Urow[0], acc.x);
    atomicAdd(&Urow[1], acc.y);
    atomicAdd(&Urow[2], acc.z);
    atomicAdd(&Urow[3], acc.w);
}

// ---------------- 7. small GEMM: out[64,512] = in[64,512] @ W[512,512] + scale_g * bias
__global__ void __launch_bounds__(128) k_mm512(const float* __restrict__ in,
                                               const float* __restrict__ W,
                                               const float* __restrict__ bias,
                                               const int* __restrict__ s1,
                                               const int* __restrict__ s2,
                                               float* __restrict__ out) {
    __shared__ float sIn[HIDDEN_C];
    int g = blockIdx.y;
    int c = blockIdx.x * 128 + threadIdx.x;
    for (int k = threadIdx.x; k < HIDDEN_C; k += 128) sIn[k] = in[g * HIDDEN_C + k];
    __syncthreads();
    float acc = 0.f;
#pragma unroll 8
    for (int k = 0; k < HIDDEN_C; k++) acc += sIn[k] * W[k * HIDDEN_C + c];
    float sc = (float)(s1[g] + (s2 ? s2[g] : 0));
    out[g * HIDDEN_C + c] = acc + bias[c] * sc;
}

// ---------------- 8. head: z = relu(pooled@Wc1+bc1); out = sigmoid(z@Wc2+bc2)
__global__ void __launch_bounds__(256) k_head(const float* __restrict__ Wc1,
                                              const float* __restrict__ bc1,
                                              const float* __restrict__ Wc2,
                                              const float* __restrict__ bc2,
                                              float* __restrict__ out) {
    int g = blockIdx.x;
    int j = threadIdx.x;  // 256
    __shared__ float sp[HIDDEN_C];
    for (int k = j; k < HIDDEN_C; k += 256) sp[k] = g_pooled[g * HIDDEN_C + k];
    __syncthreads();
    float acc = 0.f;
#pragma unroll 8
    for (int k = 0; k < HIDDEN_C; k++) acc += sp[k] * Wc1[k * 256 + j];
    float zj = fmaxf(acc + bc1[j], 0.f) * Wc2[j];
    __shared__ float red[256];
    red[j] = zj;
    __syncthreads();
    for (int ofs = 128; ofs > 0; ofs >>= 1) {
        if (j < ofs) red[j] += red[j + ofs];
        __syncthreads();
    }
    if (j == 0) {
        float s = red[0] + bc2[0];
        out[g] = 1.0f / (1.0f + expf(-s));
    }
}

// ---------------- launch ----------------
extern "C" void kernel_launch(void* const* d_in, const int* in_sizes, int n_in,
                              void* d_out, int out_size) {
    const float* x     = (const float*)d_in[0];
    const int*   ei    = (const int*)d_in[1];       // [2, E]
    const int*   batch = (const int*)d_in[2];
    const float* W_g1  = (const float*)d_in[3];
    const float* b_g1  = (const float*)d_in[4];
    const float* W_g2  = (const float*)d_in[5];
    const float* b_g2  = (const float*)d_in[6];
    const float* W_c1  = (const float*)d_in[7];
    const float* b_c1  = (const float*)d_in[8];
    const float* W_c2  = (const float*)d_in[9];
    const float* b_c2  = (const float*)d_in[10];
    float* out = (float*)d_out;

    const int* src = ei;
    const int* dst = ei + N_EDGES_C;

    // pointers to device scratch
    float *pA, *pU, *pP, *pPooled;
    int *pn, *pm;
    cudaGetSymbolAddress((void**)&pA, g_A);
    cudaGetSymbolAddress((void**)&pU, g_U);
    cudaGetSymbolAddress((void**)&pP, g_P);
    cudaGetSymbolAddress((void**)&pPooled, g_pooled);
    cudaGetSymbolAddress((void**)&pn, g_n);
    cudaGetSymbolAddress((void**)&pm, g_m);

    k_init<<<256, 256>>>();
    k_hist<<<(N_EDGES_C + 255) / 256, 256>>>(src, dst, batch);
    k_scan<<<1, 1024>>>();
    k_fill<<<(N_EDGES_C + 255) / 256, 256>>>(src, dst);
    k_gatherA<<<N_NODES_C, VEC4>>>(x);
    k_upool<<<dim3(N_GRAPHS_C, PARTS), VEC4>>>();
    // P = U @ W1 + (n+m)*b1
    k_mm512<<<dim3(HIDDEN_C / 128, N_GRAPHS_C), 128>>>(pU, W_g1, b_g1, pn, pm, pP);
    // pooled = P @ W2 + n*b2
    k_mm512<<<dim3(HIDDEN_C / 128, N_GRAPHS_C), 128>>>(pP, W_g2, b_g2, pn, (const int*)nullptr, pPooled);
    k_head<<<N_GRAPHS_C, 256>>>(W_c1, b_c1, W_c2, b_c2, out);
}